// round 4
// baseline (speedup 1.0000x reference)
#include <cuda_runtime.h>
#include <cstdint>

// GATv2 GNN, one CTA per batch element, 512 threads, all intermediates in SMEM.
// B=128, M=64, F=128; layers 1-2: H=4,C=32; layer 3: H=1,C=64.
// Round 4: split-k dual GEMM (halved weight traffic), fused register softmax,
// alpha layout [h][j][i] (EJS=68).

#define RS 132
#define NT 512
#define EJS 68
#define NEGV -1000000000.0f

#define OFF_X   0
#define OFF_XL  (64*RS)
#define OFF_XR  (2*64*RS)
#define OFF_E   (3*64*RS)
#define E_FLOATS (4*64*EJS)          // 17408
#define OFF_MS  (OFF_E + E_FLOATS)
#define OFF_SS  (OFF_MS + 512)
#define OFF_IMP (OFF_SS + 512)
#define OFF_DL  (OFF_IMP + 64)
#define OFF_DR  (OFF_DL + 256)
#define SMEM_FLOATS (OFF_DR + 256)
#define SMEM_BYTES  (SMEM_FLOATS * 4)   // 177408 B

// ---- packed f32x2 helpers (FFMA2 is PTX-only on sm_103a) ----
__device__ __forceinline__ uint64_t pk2(float lo, float hi) {
    uint64_t d; asm("mov.b64 %0, {%1, %2};" : "=l"(d) : "f"(lo), "f"(hi)); return d;
}
__device__ __forceinline__ float2 upk2(uint64_t v) {
    float lo, hi; asm("mov.b64 {%0, %1}, %2;" : "=f"(lo), "=f"(hi) : "l"(v));
    return make_float2(lo, hi);
}
__device__ __forceinline__ uint64_t fadd2(uint64_t a, uint64_t b) {
    uint64_t d; asm("add.rn.f32x2 %0, %1, %2;" : "=l"(d) : "l"(a), "l"(b)); return d;
}
__device__ __forceinline__ void ffma2(uint64_t& d, uint64_t a, uint64_t b, uint64_t c) {
    asm("fma.rn.f32x2 %0, %1, %2, %3;" : "=l"(d) : "l"(a), "l"(b), "l"(c));
}

// ---------------------------------------------------------------------------
// Split-k dual GEMM: warp w -> (kh = w&1, rowgroup = w>>1, 8 rows).
// kh==0 writes XL/XR directly; kh==1 writes partials PL/PR (dense FOUT stride).
// ---------------------------------------------------------------------------
template <int FOUT>
__device__ void dual_matmul_sk(const float* __restrict__ Wl, const float* __restrict__ Wr,
                               const float* xbuf, float* xlbuf, float* xrbuf,
                               float* PL, float* PR)
{
    const int w = threadIdx.x >> 5;
    const int lane = threadIdx.x & 31;
    const int kh = w & 1;
    const int rg = w >> 1;
    const int row0 = rg * 8;
    const int k0 = kh * 64;
    constexpr int CP2 = FOUT / 64;       // packed cols per lane: 2 or 1
    const int colbase = lane * (FOUT / 32);

    uint64_t accL[8][CP2], accR[8][CP2];
#pragma unroll
    for (int r = 0; r < 8; r++)
#pragma unroll
        for (int c = 0; c < CP2; c++) { accL[r][c] = 0ull; accR[r][c] = 0ull; }

#pragma unroll 4
    for (int kk = 0; kk < 64; kk++) {
        const int k = k0 + kk;
        uint64_t wl2[CP2], wr2[CP2];
        if constexpr (CP2 == 2) {
            ulonglong2 a = *(const ulonglong2*)(Wl + k * FOUT + colbase);
            ulonglong2 b = *(const ulonglong2*)(Wr + k * FOUT + colbase);
            wl2[0] = a.x; wl2[1] = a.y; wr2[0] = b.x; wr2[1] = b.y;
        } else {
            wl2[0] = *(const uint64_t*)(Wl + k * FOUT + colbase);
            wr2[0] = *(const uint64_t*)(Wr + k * FOUT + colbase);
        }
#pragma unroll
        for (int r = 0; r < 8; r++) {
            float xs = xbuf[(row0 + r) * RS + k];
            uint64_t xp = pk2(xs, xs);
#pragma unroll
            for (int c = 0; c < CP2; c++) {
                ffma2(accL[r][c], xp, wl2[c], accL[r][c]);
                ffma2(accR[r][c], xp, wr2[c], accR[r][c]);
            }
        }
    }
    if (kh == 0) {
#pragma unroll
        for (int r = 0; r < 8; r++) {
            if constexpr (CP2 == 2) {
                ulonglong2 sl; sl.x = accL[r][0]; sl.y = accL[r][1];
                ulonglong2 sr; sr.x = accR[r][0]; sr.y = accR[r][1];
                *(ulonglong2*)(xlbuf + (row0 + r) * RS + colbase) = sl;
                *(ulonglong2*)(xrbuf + (row0 + r) * RS + colbase) = sr;
            } else {
                *(uint64_t*)(xlbuf + (row0 + r) * RS + colbase) = accL[r][0];
                *(uint64_t*)(xrbuf + (row0 + r) * RS + colbase) = accR[r][0];
            }
        }
    } else {
#pragma unroll
        for (int r = 0; r < 8; r++) {
            if constexpr (CP2 == 2) {
                ulonglong2 sl; sl.x = accL[r][0]; sl.y = accL[r][1];
                ulonglong2 sr; sr.x = accR[r][0]; sr.y = accR[r][1];
                *(ulonglong2*)(PL + (row0 + r) * FOUT + colbase) = sl;
                *(ulonglong2*)(PR + (row0 + r) * FOUT + colbase) = sr;
            } else {
                *(uint64_t*)(PL + (row0 + r) * FOUT + colbase) = accL[r][0];
                *(uint64_t*)(PR + (row0 + r) * FOUT + colbase) = accR[r][0];
            }
        }
    }
}

template <int FOUT>
__device__ void sk_reduce(float* xlbuf, float* xrbuf, const float* PL, const float* PR)
{
    constexpr int TOT4 = 64 * FOUT / 4;
    const int t = threadIdx.x;
#pragma unroll
    for (int q = t; q < TOT4; q += NT) {
        const int row = q / (FOUT / 4);
        const int c4 = (q % (FOUT / 4)) * 4;
        float4 p = *(const float4*)(PL + row * FOUT + c4);
        float4 x = *(const float4*)(xlbuf + row * RS + c4);
        x.x += p.x; x.y += p.y; x.z += p.z; x.w += p.w;
        *(float4*)(xlbuf + row * RS + c4) = x;
        float4 pr = *(const float4*)(PR + row * FOUT + c4);
        float4 xr = *(const float4*)(xrbuf + row * RS + c4);
        xr.x += pr.x; xr.y += pr.y; xr.z += pr.z; xr.w += pr.w;
        *(float4*)(xrbuf + row * RS + c4) = xr;
    }
}

// ---------------------------------------------------------------------------
// dl[i,h] = sum_c xl[i,h,c]*att[h,c]; dr likewise. (lrelu(z)=0.6z+0.4|z|)
// ---------------------------------------------------------------------------
template <int HH, int CC>
__device__ void compute_dldr(const float* xlbuf, const float* xrbuf,
                             const float* __restrict__ att, float* DLp, float* DRp)
{
    const int t = threadIdx.x;
    if (t < 128 * HH) {
        const int which = (t >= 64 * HH) ? 1 : 0;
        const int idx = t - which * 64 * HH;
        const int h = idx % HH;
        const int i = idx / HH;
        const float* row = (which ? xrbuf : xlbuf) + i * RS + h * CC;
        const float* a = att + h * CC;
        float s0 = 0.f, s1 = 0.f, s2 = 0.f, s3 = 0.f;
#pragma unroll
        for (int c = 0; c < CC; c += 4) {
            float4 x = *(const float4*)(row + c);
            float4 av = *(const float4*)(a + c);
            s0 = fmaf(x.x, av.x, s0); s1 = fmaf(x.y, av.y, s1);
            s2 = fmaf(x.z, av.z, s2); s3 = fmaf(x.w, av.w, s3);
        }
        (which ? DRp : DLp)[idx] = (s0 + s1) + (s2 + s3);
    }
}

// ---------------------------------------------------------------------------
// compute_e + fused softmax. Thread: j=t&63, rest=t>>6 -> (h, ic).
// Per-thread chunk softmax (m,s) combined across ic-groups through MS/SS.
// Writes normalized alpha into E[h][j][i] (contiguous i, stride EJS).
// ---------------------------------------------------------------------------
template <int HH, int CC>
__device__ void compute_e_softmax(const float* xlbuf, const float* xrbuf,
                                  const float* __restrict__ att,
                                  const float* DLp, const float* DRp,
                                  float* ebuf, const int* imp, float* MS, float* SS)
{
    const int t = threadIdx.x;
    const int j = t & 63;
    const int rest = t >> 6;
    const int h = rest % HH;
    const int ic = rest / HH;
    constexpr int ICNT = 8 * HH;        // 32 (L1/2) or 8 (L3)
    const int i0 = ic * ICNT;
    constexpr uint64_t ABSM = 0x7FFFFFFF7FFFFFFFULL;

    float eacc[ICNT];
#pragma unroll
    for (int ii = 0; ii < ICNT; ii++) eacc[ii] = 0.f;

#pragma unroll
    for (int ch = 0; ch < CC / 16; ch++) {
        uint64_t xr2[8], av2[8];
        {
            const ulonglong2* xp = (const ulonglong2*)(xrbuf + j * RS + h * CC + ch * 16);
            const ulonglong2* ap = (const ulonglong2*)(att + h * CC + ch * 16);
#pragma unroll
            for (int q = 0; q < 4; q++) {
                ulonglong2 xv = xp[q]; xr2[2*q] = xv.x; xr2[2*q+1] = xv.y;
                ulonglong2 av = ap[q]; av2[2*q] = av.x; av2[2*q+1] = av.y;
            }
        }
#pragma unroll
        for (int ii = 0; ii < ICNT; ii++) {
            const ulonglong2* xl2 = (const ulonglong2*)(xlbuf + (i0 + ii) * RS + h * CC + ch * 16);
            uint64_t s2 = 0ull;
#pragma unroll
            for (int q = 0; q < 4; q++) {
                ulonglong2 xv = xl2[q];
                uint64_t z0 = fadd2(xv.x, xr2[2*q])     & ABSM;
                uint64_t z1 = fadd2(xv.y, xr2[2*q + 1]) & ABSM;
                ffma2(s2, z0, av2[2*q], s2);
                ffma2(s2, z1, av2[2*q + 1], s2);
            }
            float2 s = upk2(s2);
            eacc[ii] += s.x + s.y;
        }
    }

    // combine with linear part + mask
    const int impj = imp[j];
    const float drv = DRp[j * HH + h];
#pragma unroll
    for (int ii = 0; ii < ICNT; ii++) {
        const int i = i0 + ii;
        float e = fmaf(0.4f, eacc[ii], 0.6f * (DLp[i * HH + h] + drv));
        bool ok = (i == j) || (impj && imp[i]);
        eacc[ii] = ok ? e : NEGV;
    }

    // local softmax chunk
    float m_t = eacc[0];
#pragma unroll
    for (int ii = 1; ii < ICNT; ii++) m_t = fmaxf(m_t, eacc[ii]);
    float s_t = 0.f;
#pragma unroll
    for (int ii = 0; ii < ICNT; ii++) {
        float ex = __expf(eacc[ii] - m_t);
        eacc[ii] = ex;
        s_t += ex;
    }
    MS[t] = m_t; SS[t] = s_t;
    __syncthreads();

    // global combine over ic groups
    constexpr int NG = 8 / HH;          // 2 or 8
    const int base = t & (64 * HH - 1);
    float M = -3.4e38f;
    float mg[NG], sg[NG];
#pragma unroll
    for (int g = 0; g < NG; g++) {
        mg[g] = MS[base + g * 64 * HH];
        sg[g] = SS[base + g * 64 * HH];
        M = fmaxf(M, mg[g]);
    }
    float S = 0.f;
#pragma unroll
    for (int g = 0; g < NG; g++) S = fmaf(sg[g], __expf(mg[g] - M), S);
    const float kfac = __expf(m_t - M) / S;

    float* dst = ebuf + (h * 64 + j) * EJS + i0;
#pragma unroll
    for (int ii = 0; ii < ICNT; ii += 4) {
        float4 o;
        o.x = eacc[ii] * kfac;     o.y = eacc[ii + 1] * kfac;
        o.z = eacc[ii + 2] * kfac; o.w = eacc[ii + 3] * kfac;
        *(float4*)(dst + ii) = o;
    }
}

// ---------------------------------------------------------------------------
// out[j][f] = sum_i alpha[h][j][i] * xl[i][f] + bias[f]
// Thread: j = t&63, fs = t>>6 (8 slices of FOUT/8 floats).
// ---------------------------------------------------------------------------
template <int CC, int FOUT>
__device__ void aggregate(const float* xlbuf, const float* ebuf,
                          const float* __restrict__ bias, float* dst, int ds)
{
    const int t = threadIdx.x;
    const int j = t & 63;
    const int fs = t >> 6;
    constexpr int FW = FOUT / 8;        // 16 or 8
    const int f0 = fs * FW;
    const int h = f0 / CC;
    const float* arow = ebuf + (h * 64 + j) * EJS;

    uint64_t acc[FW / 2];
#pragma unroll
    for (int c = 0; c < FW / 2; c++) acc[c] = 0ull;

#pragma unroll 2
    for (int ib = 0; ib < 64; ib += 4) {
        float4 a4 = *(const float4*)(arow + ib);
#pragma unroll
        for (int u = 0; u < 4; u++) {
            float as = (u == 0) ? a4.x : (u == 1) ? a4.y : (u == 2) ? a4.z : a4.w;
            uint64_t ap = pk2(as, as);
            const float* xlr = xlbuf + (ib + u) * RS + f0;
#pragma unroll
            for (int c = 0; c < FW / 2; c += 2) {
                ulonglong2 xv = *(const ulonglong2*)(xlr + c * 2);
                ffma2(acc[c],     ap, xv.x, acc[c]);
                ffma2(acc[c + 1], ap, xv.y, acc[c + 1]);
            }
        }
    }
#pragma unroll
    for (int c = 0; c < FW / 2; c += 2) {
        float2 lo = upk2(acc[c]);
        float2 hi = upk2(acc[c + 1]);
        float4 bv = *(const float4*)(bias + f0 + c * 2);
        float4 o;
        o.x = lo.x + bv.x; o.y = lo.y + bv.y;
        o.z = hi.x + bv.z; o.w = hi.y + bv.w;
        *(float4*)(dst + j * ds + f0 + c * 2) = o;
    }
}

// layernorm over 128 features + relu, in place. Warp per row, 4 rows per warp.
__device__ void ln_relu(float* xbuf, const float* __restrict__ g, const float* __restrict__ bb)
{
    const int w = threadIdx.x >> 5;
    const int lane = threadIdx.x & 31;
    for (int r = w; r < 64; r += 16) {
        float4 v = *(const float4*)(xbuf + r * RS + lane * 4);
        float sum = v.x + v.y + v.z + v.w;
        float sq  = v.x*v.x + v.y*v.y + v.z*v.z + v.w*v.w;
#pragma unroll
        for (int o = 16; o > 0; o >>= 1) {
            sum += __shfl_xor_sync(0xffffffffu, sum, o);
            sq  += __shfl_xor_sync(0xffffffffu, sq, o);
        }
        float mean = sum * (1.f / 128.f);
        float var  = sq * (1.f / 128.f) - mean * mean;
        float rstd = rsqrtf(var + 1e-5f);
        float4 gg = *(const float4*)(g + lane * 4);
        float4 bv = *(const float4*)(bb + lane * 4);
        float4 o;
        o.x = fmaxf((v.x - mean) * rstd * gg.x + bv.x, 0.f);
        o.y = fmaxf((v.y - mean) * rstd * gg.y + bv.y, 0.f);
        o.z = fmaxf((v.z - mean) * rstd * gg.z + bv.z, 0.f);
        o.w = fmaxf((v.w - mean) * rstd * gg.w + bv.w, 0.f);
        *(float4*)(xbuf + r * RS + lane * 4) = o;
    }
}

__global__ void __launch_bounds__(NT, 1)
GNN_61040075210810_kernel(
    const float* __restrict__ team_obs, const float* __restrict__ target_obs,
    const float* __restrict__ team_mask, const float* __restrict__ ltm,
    const float* __restrict__ W_emb, const float* __restrict__ b_emb,
    const float* __restrict__ Wl1, const float* __restrict__ Wr1,
    const float* __restrict__ att1, const float* __restrict__ b1,
    const float* __restrict__ Wl2, const float* __restrict__ Wr2,
    const float* __restrict__ att2, const float* __restrict__ b2,
    const float* __restrict__ Wl3, const float* __restrict__ Wr3,
    const float* __restrict__ att3, const float* __restrict__ b3,
    const float* __restrict__ ln1g, const float* __restrict__ ln1b,
    const float* __restrict__ ln2g, const float* __restrict__ ln2b,
    float* __restrict__ out)
{
    extern __shared__ float smf[];
    float* X  = smf + OFF_X;
    float* XL = smf + OFF_XL;
    float* XR = smf + OFF_XR;
    float* E  = smf + OFF_E;            // alpha [h][j][i], EJS stride; also FIN/PART alias
    float* MS = smf + OFF_MS;
    float* SS = smf + OFF_SS;
    int*   IMP = (int*)(smf + OFF_IMP);
    float* DL = smf + OFF_DL;
    float* DR = smf + OFF_DR;

    const int b = blockIdx.x;
    const int t = threadIdx.x;

    // ---- feature assembly: fin (64 x 16) aliased into E ----
    float* FIN = E;
    for (int idx = t; idx < 1024; idx += NT) {
        int m = idx >> 4, k = idx & 15;
        float v;
        if (m < 16) {
            v = (k < 14) ? team_obs[(b * 16 + m) * 14 + k] : 0.f;
        } else {
            int tt = m - 16;
            if (k < 12)      v = target_obs[(b * 48 + tt) * 15 + k];
            else if (k < 14) v = 0.f;
            else             v = target_obs[(b * 48 + tt) * 15 + (k - 2)];
        }
        FIN[idx] = v;
    }
    if (t < 64) {
        bool ok = (t < 16) ? (team_mask[b * 32 + t] != NEGV)
                           : (ltm[b * 49 + (t - 16)] != 0.0f);
        IMP[t] = ok ? 1 : 0;
    }
    __syncthreads();

    // ---- embedding: X = FIN @ W_emb + b_emb  (64x16 @ 16x128) ----
    {
        const int w = t >> 5, lane = t & 31;
        const int row0 = w * 4;
        float acc[4][4];
#pragma unroll
        for (int r = 0; r < 4; r++)
#pragma unroll
            for (int c = 0; c < 4; c++) acc[r][c] = 0.f;
#pragma unroll
        for (int k = 0; k < 16; k++) {
            float xv[4];
#pragma unroll
            for (int r = 0; r < 4; r++) xv[r] = FIN[(row0 + r) * 16 + k];
            float4 wv = *(const float4*)(W_emb + k * 128 + lane * 4);
#pragma unroll
            for (int r = 0; r < 4; r++) {
                acc[r][0] = fmaf(xv[r], wv.x, acc[r][0]);
                acc[r][1] = fmaf(xv[r], wv.y, acc[r][1]);
                acc[r][2] = fmaf(xv[r], wv.z, acc[r][2]);
                acc[r][3] = fmaf(xv[r], wv.w, acc[r][3]);
            }
        }
        float4 be = *(const float4*)(b_emb + lane * 4);
#pragma unroll
        for (int r = 0; r < 4; r++) {
            float4 o;
            o.x = acc[r][0] + be.x; o.y = acc[r][1] + be.y;
            o.z = acc[r][2] + be.z; o.w = acc[r][3] + be.w;
            *(float4*)(X + (row0 + r) * RS + lane * 4) = o;
        }
    }
    __syncthreads();

    float* PL = E;                       // split-k partial buffers alias E
    float* PR128 = E + 64 * 128;
    float* PR64  = E + 64 * 64;

    // ---- layer 1 ----
    dual_matmul_sk<128>(Wl1, Wr1, X, XL, XR, PL, PR128);
    __syncthreads();
    sk_reduce<128>(XL, XR, PL, PR128);
    __syncthreads();
    compute_dldr<4, 32>(XL, XR, att1, DL, DR);
    __syncthreads();
    compute_e_softmax<4, 32>(XL, XR, att1, DL, DR, E, IMP, MS, SS);
    __syncthreads();
    aggregate<32, 128>(XL, E, b1, X, RS);
    __syncthreads();
    ln_relu(X, ln1g, ln1b);
    __syncthreads();

    // ---- layer 2 ----
    dual_matmul_sk<128>(Wl2, Wr2, X, XL, XR, PL, PR128);
    __syncthreads();
    sk_reduce<128>(XL, XR, PL, PR128);
    __syncthreads();
    compute_dldr<4, 32>(XL, XR, att2, DL, DR);
    __syncthreads();
    compute_e_softmax<4, 32>(XL, XR, att2, DL, DR, E, IMP, MS, SS);
    __syncthreads();
    aggregate<32, 128>(XL, E, b2, X, RS);
    __syncthreads();
    ln_relu(X, ln2g, ln2b);
    __syncthreads();

    // ---- layer 3 (H=1, C=64) ----
    dual_matmul_sk<64>(Wl3, Wr3, X, XL, XR, PL, PR64);
    __syncthreads();
    sk_reduce<64>(XL, XR, PL, PR64);
    __syncthreads();
    compute_dldr<1, 64>(XL, XR, att3, DL, DR);
    __syncthreads();
    compute_e_softmax<1, 64>(XL, XR, att3, DL, DR, E, IMP, MS, SS);
    __syncthreads();
    aggregate<64, 64>(XL, E, b3, out + b * 64 * 64, 64);
}

extern "C" void kernel_launch(void* const* d_in, const int* in_sizes, int n_in,
                              void* d_out, int out_size)
{
    (void)in_sizes; (void)n_in; (void)out_size;
    cudaFuncSetAttribute(GNN_61040075210810_kernel,
                         cudaFuncAttributeMaxDynamicSharedMemorySize, SMEM_BYTES);
    GNN_61040075210810_kernel<<<128, NT, SMEM_BYTES>>>(
        (const float*)d_in[0],  (const float*)d_in[1],
        (const float*)d_in[2],  (const float*)d_in[3],
        (const float*)d_in[4],  (const float*)d_in[5],
        (const float*)d_in[6],  (const float*)d_in[7],
        (const float*)d_in[8],  (const float*)d_in[9],
        (const float*)d_in[10], (const float*)d_in[11],
        (const float*)d_in[12], (const float*)d_in[13],
        (const float*)d_in[14], (const float*)d_in[15],
        (const float*)d_in[16], (const float*)d_in[17],
        (const float*)d_in[18], (const float*)d_in[19],
        (const float*)d_in[20], (const float*)d_in[21],
        (float*)d_out);
}

// round 5
// speedup vs baseline: 1.0298x; 1.0298x over previous
#include <cuda_runtime.h>
#include <cstdint>

// GATv2 GNN, one CTA per batch element, 512 threads, all intermediates in SMEM.
// B=128, M=64, F=128; layers 1-2: H=4,C=32; layer 3: H=1,C=64.
// Round 5: full-k dual GEMM (split-k reverted) with float4 x-loads,
// fused register softmax, alpha layout [h][j][i] (EJS=68).

#define RS 132
#define NT 512
#define EJS 68
#define NEGV -1000000000.0f

#define OFF_X   0
#define OFF_XL  (64*RS)
#define OFF_XR  (2*64*RS)
#define OFF_E   (3*64*RS)
#define E_FLOATS (4*64*EJS)          // 17408
#define OFF_MS  (OFF_E + E_FLOATS)
#define OFF_SS  (OFF_MS + 512)
#define OFF_IMP (OFF_SS + 512)
#define OFF_DL  (OFF_IMP + 64)
#define OFF_DR  (OFF_DL + 256)
#define SMEM_FLOATS (OFF_DR + 256)
#define SMEM_BYTES  (SMEM_FLOATS * 4)   // 177408 B

// ---- packed f32x2 helpers (FFMA2 is PTX-only on sm_103a) ----
__device__ __forceinline__ uint64_t pk2(float lo, float hi) {
    uint64_t d; asm("mov.b64 %0, {%1, %2};" : "=l"(d) : "f"(lo), "f"(hi)); return d;
}
__device__ __forceinline__ float2 upk2(uint64_t v) {
    float lo, hi; asm("mov.b64 {%0, %1}, %2;" : "=f"(lo), "=f"(hi) : "l"(v));
    return make_float2(lo, hi);
}
__device__ __forceinline__ uint64_t fadd2(uint64_t a, uint64_t b) {
    uint64_t d; asm("add.rn.f32x2 %0, %1, %2;" : "=l"(d) : "l"(a), "l"(b)); return d;
}
__device__ __forceinline__ void ffma2(uint64_t& d, uint64_t a, uint64_t b, uint64_t c) {
    asm("fma.rn.f32x2 %0, %1, %2, %3;" : "=l"(d) : "l"(a), "l"(b), "l"(c));
}

// ---------------------------------------------------------------------------
// xl = x @ Wl, xr = x @ Wr. 16 warps x 4 rows, lane covers FOUT/32 columns,
// packed FFMA2; x loaded as float4 per 4 k-steps (LDS.128 broadcast).
// ---------------------------------------------------------------------------
template <int FOUT>
__device__ void dual_matmul(const float* __restrict__ Wl, const float* __restrict__ Wr,
                            const float* xbuf, float* xlbuf, float* xrbuf)
{
    const int w = threadIdx.x >> 5;
    const int lane = threadIdx.x & 31;
    constexpr int CP2 = FOUT / 64;      // packed cols per lane: 2 or 1
    const int row0 = w * 4;
    const int colbase = lane * (FOUT / 32);

    uint64_t accL[4][CP2], accR[4][CP2];
#pragma unroll
    for (int r = 0; r < 4; r++)
#pragma unroll
        for (int c = 0; c < CP2; c++) { accL[r][c] = 0ull; accR[r][c] = 0ull; }

#pragma unroll 2
    for (int k4 = 0; k4 < 128; k4 += 4) {
        float4 xk[4];
#pragma unroll
        for (int r = 0; r < 4; r++)
            xk[r] = *(const float4*)(xbuf + (row0 + r) * RS + k4);
#pragma unroll
        for (int u = 0; u < 4; u++) {
            const int k = k4 + u;
            uint64_t wl2[CP2], wr2[CP2];
            if constexpr (CP2 == 2) {
                ulonglong2 a = *(const ulonglong2*)(Wl + k * FOUT + colbase);
                ulonglong2 bq = *(const ulonglong2*)(Wr + k * FOUT + colbase);
                wl2[0] = a.x; wl2[1] = a.y; wr2[0] = bq.x; wr2[1] = bq.y;
            } else {
                wl2[0] = *(const uint64_t*)(Wl + k * FOUT + colbase);
                wr2[0] = *(const uint64_t*)(Wr + k * FOUT + colbase);
            }
#pragma unroll
            for (int r = 0; r < 4; r++) {
                float xs = (u == 0) ? xk[r].x : (u == 1) ? xk[r].y
                         : (u == 2) ? xk[r].z : xk[r].w;
                uint64_t xp = pk2(xs, xs);
#pragma unroll
                for (int c = 0; c < CP2; c++) {
                    ffma2(accL[r][c], xp, wl2[c], accL[r][c]);
                    ffma2(accR[r][c], xp, wr2[c], accR[r][c]);
                }
            }
        }
    }
#pragma unroll
    for (int r = 0; r < 4; r++) {
        if constexpr (CP2 == 2) {
            ulonglong2 sl; sl.x = accL[r][0]; sl.y = accL[r][1];
            ulonglong2 sr; sr.x = accR[r][0]; sr.y = accR[r][1];
            *(ulonglong2*)(xlbuf + (row0 + r) * RS + colbase) = sl;
            *(ulonglong2*)(xrbuf + (row0 + r) * RS + colbase) = sr;
        } else {
            *(uint64_t*)(xlbuf + (row0 + r) * RS + colbase) = accL[r][0];
            *(uint64_t*)(xrbuf + (row0 + r) * RS + colbase) = accR[r][0];
        }
    }
}

// ---------------------------------------------------------------------------
// dl[i,h] = sum_c xl[i,h,c]*att[h,c]; dr likewise. (lrelu(z)=0.6z+0.4|z|)
// ---------------------------------------------------------------------------
template <int HH, int CC>
__device__ void compute_dldr(const float* xlbuf, const float* xrbuf,
                             const float* __restrict__ att, float* DLp, float* DRp)
{
    const int t = threadIdx.x;
    if (t < 128 * HH) {
        const int which = (t >= 64 * HH) ? 1 : 0;
        const int idx = t - which * 64 * HH;
        const int h = idx % HH;
        const int i = idx / HH;
        const float* row = (which ? xrbuf : xlbuf) + i * RS + h * CC;
        const float* a = att + h * CC;
        float s0 = 0.f, s1 = 0.f, s2 = 0.f, s3 = 0.f;
#pragma unroll
        for (int c = 0; c < CC; c += 4) {
            float4 x = *(const float4*)(row + c);
            float4 av = *(const float4*)(a + c);
            s0 = fmaf(x.x, av.x, s0); s1 = fmaf(x.y, av.y, s1);
            s2 = fmaf(x.z, av.z, s2); s3 = fmaf(x.w, av.w, s3);
        }
        (which ? DRp : DLp)[idx] = (s0 + s1) + (s2 + s3);
    }
}

// ---------------------------------------------------------------------------
// compute_e + fused softmax. Thread: j=t&63, rest=t>>6 -> (h, ic).
// Per-thread chunk softmax (m,s) combined across ic-groups through MS/SS.
// Writes normalized alpha into E[h][j][i] (contiguous i, stride EJS).
// ---------------------------------------------------------------------------
template <int HH, int CC>
__device__ void compute_e_softmax(const float* xlbuf, const float* xrbuf,
                                  const float* __restrict__ att,
                                  const float* DLp, const float* DRp,
                                  float* ebuf, const int* imp, float* MS, float* SS)
{
    const int t = threadIdx.x;
    const int j = t & 63;
    const int rest = t >> 6;
    const int h = rest % HH;
    const int ic = rest / HH;
    constexpr int ICNT = 8 * HH;        // 32 (L1/2) or 8 (L3)
    const int i0 = ic * ICNT;
    constexpr uint64_t ABSM = 0x7FFFFFFF7FFFFFFFULL;

    float eacc[ICNT];
#pragma unroll
    for (int ii = 0; ii < ICNT; ii++) eacc[ii] = 0.f;

#pragma unroll
    for (int ch = 0; ch < CC / 16; ch++) {
        uint64_t xr2[8], av2[8];
        {
            const ulonglong2* xp = (const ulonglong2*)(xrbuf + j * RS + h * CC + ch * 16);
            const ulonglong2* ap = (const ulonglong2*)(att + h * CC + ch * 16);
#pragma unroll
            for (int q = 0; q < 4; q++) {
                ulonglong2 xv = xp[q]; xr2[2*q] = xv.x; xr2[2*q+1] = xv.y;
                ulonglong2 av = ap[q]; av2[2*q] = av.x; av2[2*q+1] = av.y;
            }
        }
#pragma unroll
        for (int ii = 0; ii < ICNT; ii++) {
            const ulonglong2* xl2 = (const ulonglong2*)(xlbuf + (i0 + ii) * RS + h * CC + ch * 16);
            uint64_t s2 = 0ull;
#pragma unroll
            for (int q = 0; q < 4; q++) {
                ulonglong2 xv = xl2[q];
                uint64_t z0 = fadd2(xv.x, xr2[2*q])     & ABSM;
                uint64_t z1 = fadd2(xv.y, xr2[2*q + 1]) & ABSM;
                ffma2(s2, z0, av2[2*q], s2);
                ffma2(s2, z1, av2[2*q + 1], s2);
            }
            float2 s = upk2(s2);
            eacc[ii] += s.x + s.y;
        }
    }

    // combine with linear part + mask
    const int impj = imp[j];
    const float drv = DRp[j * HH + h];
#pragma unroll
    for (int ii = 0; ii < ICNT; ii++) {
        const int i = i0 + ii;
        float e = fmaf(0.4f, eacc[ii], 0.6f * (DLp[i * HH + h] + drv));
        bool ok = (i == j) || (impj && imp[i]);
        eacc[ii] = ok ? e : NEGV;
    }

    // local softmax chunk
    float m_t = eacc[0];
#pragma unroll
    for (int ii = 1; ii < ICNT; ii++) m_t = fmaxf(m_t, eacc[ii]);
    float s_t = 0.f;
#pragma unroll
    for (int ii = 0; ii < ICNT; ii++) {
        float ex = __expf(eacc[ii] - m_t);
        eacc[ii] = ex;
        s_t += ex;
    }
    MS[t] = m_t; SS[t] = s_t;
    __syncthreads();

    // global combine over ic groups
    constexpr int NG = 8 / HH;          // 2 or 8
    const int base = t & (64 * HH - 1);
    float M = -3.4e38f;
    float mg[NG], sg[NG];
#pragma unroll
    for (int g = 0; g < NG; g++) {
        mg[g] = MS[base + g * 64 * HH];
        sg[g] = SS[base + g * 64 * HH];
        M = fmaxf(M, mg[g]);
    }
    float S = 0.f;
#pragma unroll
    for (int g = 0; g < NG; g++) S = fmaf(sg[g], __expf(mg[g] - M), S);
    const float kfac = __expf(m_t - M) / S;

    float* dst = ebuf + (h * 64 + j) * EJS + i0;
#pragma unroll
    for (int ii = 0; ii < ICNT; ii += 4) {
        float4 o;
        o.x = eacc[ii] * kfac;     o.y = eacc[ii + 1] * kfac;
        o.z = eacc[ii + 2] * kfac; o.w = eacc[ii + 3] * kfac;
        *(float4*)(dst + ii) = o;
    }
}

// ---------------------------------------------------------------------------
// out[j][f] = sum_i alpha[h][j][i] * xl[i][f] + bias[f]
// Thread: j = t&63, fs = t>>6 (8 slices of FOUT/8 floats).
// ---------------------------------------------------------------------------
template <int CC, int FOUT>
__device__ void aggregate(const float* xlbuf, const float* ebuf,
                          const float* __restrict__ bias, float* dst, int ds)
{
    const int t = threadIdx.x;
    const int j = t & 63;
    const int fs = t >> 6;
    constexpr int FW = FOUT / 8;        // 16 or 8
    const int f0 = fs * FW;
    const int h = f0 / CC;
    const float* arow = ebuf + (h * 64 + j) * EJS;

    uint64_t acc[FW / 2];
#pragma unroll
    for (int c = 0; c < FW / 2; c++) acc[c] = 0ull;

#pragma unroll 2
    for (int ib = 0; ib < 64; ib += 4) {
        float4 a4 = *(const float4*)(arow + ib);
#pragma unroll
        for (int u = 0; u < 4; u++) {
            float as = (u == 0) ? a4.x : (u == 1) ? a4.y : (u == 2) ? a4.z : a4.w;
            uint64_t ap = pk2(as, as);
            const float* xlr = xlbuf + (ib + u) * RS + f0;
#pragma unroll
            for (int c = 0; c < FW / 2; c += 2) {
                ulonglong2 xv = *(const ulonglong2*)(xlr + c * 2);
                ffma2(acc[c],     ap, xv.x, acc[c]);
                ffma2(acc[c + 1], ap, xv.y, acc[c + 1]);
            }
        }
    }
#pragma unroll
    for (int c = 0; c < FW / 2; c += 2) {
        float2 lo = upk2(acc[c]);
        float2 hi = upk2(acc[c + 1]);
        float4 bv = *(const float4*)(bias + f0 + c * 2);
        float4 o;
        o.x = lo.x + bv.x; o.y = lo.y + bv.y;
        o.z = hi.x + bv.z; o.w = hi.y + bv.w;
        *(float4*)(dst + j * ds + f0 + c * 2) = o;
    }
}

// layernorm over 128 features + relu, in place. Warp per row, 4 rows per warp.
__device__ void ln_relu(float* xbuf, const float* __restrict__ g, const float* __restrict__ bb)
{
    const int w = threadIdx.x >> 5;
    const int lane = threadIdx.x & 31;
    for (int r = w; r < 64; r += 16) {
        float4 v = *(const float4*)(xbuf + r * RS + lane * 4);
        float sum = v.x + v.y + v.z + v.w;
        float sq  = v.x*v.x + v.y*v.y + v.z*v.z + v.w*v.w;
#pragma unroll
        for (int o = 16; o > 0; o >>= 1) {
            sum += __shfl_xor_sync(0xffffffffu, sum, o);
            sq  += __shfl_xor_sync(0xffffffffu, sq, o);
        }
        float mean = sum * (1.f / 128.f);
        float var  = sq * (1.f / 128.f) - mean * mean;
        float rstd = rsqrtf(var + 1e-5f);
        float4 gg = *(const float4*)(g + lane * 4);
        float4 bv = *(const float4*)(bb + lane * 4);
        float4 o;
        o.x = fmaxf((v.x - mean) * rstd * gg.x + bv.x, 0.f);
        o.y = fmaxf((v.y - mean) * rstd * gg.y + bv.y, 0.f);
        o.z = fmaxf((v.z - mean) * rstd * gg.z + bv.z, 0.f);
        o.w = fmaxf((v.w - mean) * rstd * gg.w + bv.w, 0.f);
        *(float4*)(xbuf + r * RS + lane * 4) = o;
    }
}

__global__ void __launch_bounds__(NT, 1)
GNN_61040075210810_kernel(
    const float* __restrict__ team_obs, const float* __restrict__ target_obs,
    const float* __restrict__ team_mask, const float* __restrict__ ltm,
    const float* __restrict__ W_emb, const float* __restrict__ b_emb,
    const float* __restrict__ Wl1, const float* __restrict__ Wr1,
    const float* __restrict__ att1, const float* __restrict__ b1,
    const float* __restrict__ Wl2, const float* __restrict__ Wr2,
    const float* __restrict__ att2, const float* __restrict__ b2,
    const float* __restrict__ Wl3, const float* __restrict__ Wr3,
    const float* __restrict__ att3, const float* __restrict__ b3,
    const float* __restrict__ ln1g, const float* __restrict__ ln1b,
    const float* __restrict__ ln2g, const float* __restrict__ ln2b,
    float* __restrict__ out)
{
    extern __shared__ float smf[];
    float* X  = smf + OFF_X;
    float* XL = smf + OFF_XL;
    float* XR = smf + OFF_XR;
    float* E  = smf + OFF_E;            // alpha [h][j][i], EJS stride; FIN alias
    float* MS = smf + OFF_MS;
    float* SS = smf + OFF_SS;
    int*   IMP = (int*)(smf + OFF_IMP);
    float* DL = smf + OFF_DL;
    float* DR = smf + OFF_DR;

    const int b = blockIdx.x;
    const int t = threadIdx.x;

    // ---- feature assembly: fin (64 x 16) aliased into E ----
    float* FIN = E;
    for (int idx = t; idx < 1024; idx += NT) {
        int m = idx >> 4, k = idx & 15;
        float v;
        if (m < 16) {
            v = (k < 14) ? team_obs[(b * 16 + m) * 14 + k] : 0.f;
        } else {
            int tt = m - 16;
            if (k < 12)      v = target_obs[(b * 48 + tt) * 15 + k];
            else if (k < 14) v = 0.f;
            else             v = target_obs[(b * 48 + tt) * 15 + (k - 2)];
        }
        FIN[idx] = v;
    }
    if (t < 64) {
        bool ok = (t < 16) ? (team_mask[b * 32 + t] != NEGV)
                           : (ltm[b * 49 + (t - 16)] != 0.0f);
        IMP[t] = ok ? 1 : 0;
    }
    __syncthreads();

    // ---- embedding: X = FIN @ W_emb + b_emb  (64x16 @ 16x128) ----
    {
        const int w = t >> 5, lane = t & 31;
        const int row0 = w * 4;
        float acc[4][4];
#pragma unroll
        for (int r = 0; r < 4; r++)
#pragma unroll
            for (int c = 0; c < 4; c++) acc[r][c] = 0.f;
#pragma unroll
        for (int k = 0; k < 16; k++) {
            float xv[4];
#pragma unroll
            for (int r = 0; r < 4; r++) xv[r] = FIN[(row0 + r) * 16 + k];
            float4 wv = *(const float4*)(W_emb + k * 128 + lane * 4);
#pragma unroll
            for (int r = 0; r < 4; r++) {
                acc[r][0] = fmaf(xv[r], wv.x, acc[r][0]);
                acc[r][1] = fmaf(xv[r], wv.y, acc[r][1]);
                acc[r][2] = fmaf(xv[r], wv.z, acc[r][2]);
                acc[r][3] = fmaf(xv[r], wv.w, acc[r][3]);
            }
        }
        float4 be = *(const float4*)(b_emb + lane * 4);
#pragma unroll
        for (int r = 0; r < 4; r++) {
            float4 o;
            o.x = acc[r][0] + be.x; o.y = acc[r][1] + be.y;
            o.z = acc[r][2] + be.z; o.w = acc[r][3] + be.w;
            *(float4*)(X + (row0 + r) * RS + lane * 4) = o;
        }
    }
    __syncthreads();

    // ---- layer 1 ----
    dual_matmul<128>(Wl1, Wr1, X, XL, XR);
    __syncthreads();
    compute_dldr<4, 32>(XL, XR, att1, DL, DR);
    __syncthreads();
    compute_e_softmax<4, 32>(XL, XR, att1, DL, DR, E, IMP, MS, SS);
    __syncthreads();
    aggregate<32, 128>(XL, E, b1, X, RS);
    __syncthreads();
    ln_relu(X, ln1g, ln1b);
    __syncthreads();

    // ---- layer 2 ----
    dual_matmul<128>(Wl2, Wr2, X, XL, XR);
    __syncthreads();
    compute_dldr<4, 32>(XL, XR, att2, DL, DR);
    __syncthreads();
    compute_e_softmax<4, 32>(XL, XR, att2, DL, DR, E, IMP, MS, SS);
    __syncthreads();
    aggregate<32, 128>(XL, E, b2, X, RS);
    __syncthreads();
    ln_relu(X, ln2g, ln2b);
    __syncthreads();

    // ---- layer 3 (H=1, C=64) ----
    dual_matmul<64>(Wl3, Wr3, X, XL, XR);
    __syncthreads();
    compute_dldr<1, 64>(XL, XR, att3, DL, DR);
    __syncthreads();
    compute_e_softmax<1, 64>(XL, XR, att3, DL, DR, E, IMP, MS, SS);
    __syncthreads();
    aggregate<64, 64>(XL, E, b3, out + b * 64 * 64, 64);
}

extern "C" void kernel_launch(void* const* d_in, const int* in_sizes, int n_in,
                              void* d_out, int out_size)
{
    (void)in_sizes; (void)n_in; (void)out_size;
    cudaFuncSetAttribute(GNN_61040075210810_kernel,
                         cudaFuncAttributeMaxDynamicSharedMemorySize, SMEM_BYTES);
    GNN_61040075210810_kernel<<<128, NT, SMEM_BYTES>>>(
        (const float*)d_in[0],  (const float*)d_in[1],
        (const float*)d_in[2],  (const float*)d_in[3],
        (const float*)d_in[4],  (const float*)d_in[5],
        (const float*)d_in[6],  (const float*)d_in[7],
        (const float*)d_in[8],  (const float*)d_in[9],
        (const float*)d_in[10], (const float*)d_in[11],
        (const float*)d_in[12], (const float*)d_in[13],
        (const float*)d_in[14], (const float*)d_in[15],
        (const float*)d_in[16], (const float*)d_in[17],
        (const float*)d_in[18], (const float*)d_in[19],
        (const float*)d_in[20], (const float*)d_in[21],
        (float*)d_out);
}